// round 2
// baseline (speedup 1.0000x reference)
#include <cuda_runtime.h>
#include <cstdint>
#include <cstddef>

#define T_SEQ 512
#define BATCH 128
#define DIN   1024
#define DOUT  1024
#define N4    4096          // 4 gates * DOUT, gate-interleaved: n = unit*4 + gate
#define GRID_LSTM 128

// ---------------- static device scratch (no allocations allowed) ----------------
__device__ __align__(256) float g_Z  [(size_t)T_SEQ * BATCH * N4];   // 1 GiB: x-part preactivations (+bias)
__device__ __align__(256) float g_Wx [(size_t)N4 * DIN];             // packed tf32-rounded x-weights
__device__ __align__(256) float g_Wh [(size_t)N4 * DOUT];            // packed tf32-rounded h-weights
__device__ __align__(256) float g_bias[N4];
__device__ __align__(256) float g_Xhi[(size_t)T_SEQ * BATCH * DIN];  // tf32 hi split of tokens
__device__ __align__(256) float g_Xlo[(size_t)T_SEQ * BATCH * DIN];  // tf32 lo split of tokens
__device__ __align__(256) float g_h  [2][BATCH * DOUT];              // ping-pong hidden state (tf32-rounded)
__device__ unsigned g_bar;                                           // grid barrier counter

// ---------------- helpers ----------------
__device__ __forceinline__ float tf32r(float x) {
    uint32_t u;
    asm("cvt.rna.tf32.f32 %0, %1;" : "=r"(u) : "f"(x));
    return __uint_as_float(u);
}

__device__ __forceinline__ void cp16(float* smem_dst, const float* gsrc) {
    unsigned s = (unsigned)__cvta_generic_to_shared(smem_dst);
    asm volatile("cp.async.cg.shared.global [%0], [%1], 16;\n" :: "r"(s), "l"(gsrc));
}

__device__ __forceinline__ void mma8(float* d, const unsigned* a, const unsigned* b) {
    asm volatile(
        "mma.sync.aligned.m16n8k8.row.col.f32.tf32.tf32.f32 "
        "{%0,%1,%2,%3}, {%4,%5,%6,%7}, {%8,%9}, {%0,%1,%2,%3};\n"
        : "+f"(d[0]), "+f"(d[1]), "+f"(d[2]), "+f"(d[3])
        : "r"(a[0]), "r"(a[1]), "r"(a[2]), "r"(a[3]), "r"(b[0]), "r"(b[1]));
}

__device__ __forceinline__ float sigm(float x) { return 1.f / (1.f + __expf(-x)); }

#define SAS 36                // smem row stride (floats) for 32-wide K chunks

// ---------------- kernel 1: pack weights / split tokens / reset state ----------------
__global__ void __launch_bounds__(256) pack_kernel(
    const float* __restrict__ tokens,
    const float* __restrict__ Wf, const float* __restrict__ bf,
    const float* __restrict__ Wi, const float* __restrict__ bi,
    const float* __restrict__ Wc, const float* __restrict__ bc,
    const float* __restrict__ Wo, const float* __restrict__ bo)
{
    size_t tid = (size_t)blockIdx.x * blockDim.x + threadIdx.x;
    size_t nth = (size_t)gridDim.x * blockDim.x;
    if (tid == 0) g_bar = 0;   // reset grid barrier every launch (graph replays)

    for (size_t i = tid; i < (size_t)N4 * 1024; i += nth) {
        int n = (int)(i >> 10), k = (int)(i & 1023);
        int u = n >> 2, g = n & 3;
        const float* W = (g == 0) ? Wf : (g == 1) ? Wi : (g == 2) ? Wc : Wo;
        g_Wx[i] = tf32r(W[(size_t)u * 2048 + k]);
        g_Wh[i] = tf32r(W[(size_t)u * 2048 + 1024 + k]);
    }
    for (size_t i = tid; i < (size_t)N4; i += nth) {
        int u = (int)(i >> 2), g = (int)(i & 3);
        const float* bb = (g == 0) ? bf : (g == 1) ? bi : (g == 2) ? bc : bo;
        g_bias[i] = bb[u];
    }
    for (size_t i = tid; i < (size_t)T_SEQ * BATCH * DIN; i += nth) {
        float x  = tokens[i];
        float hi = tf32r(x);
        g_Xhi[i] = hi;
        g_Xlo[i] = tf32r(x - hi);
    }
    for (size_t i = tid; i < (size_t)BATCH * DOUT; i += nth)
        g_h[0][i] = 0.f;   // h0 = 0
}

// ---------------- kernel 2: Z = (Xhi+Xlo) @ Wx^T + b, 128x128 tiles, fused hi/lo ----------------
// 256 threads = 8 warps as 2(M) x 4(N); warp tile 64x32; K chunks of 32.
#define PC_TILE_F (128 * SAS)                    // floats per (128 x 32) chunk
#define PC_SMEM   (6 * PC_TILE_F * 4)            // Ahi/Alo/B double-buffered, bytes

__device__ __forceinline__ void pc_load(float* s, const float* g, int tid) {
    // 128 rows x 32 floats = 1024 cp16 / 256 threads
    #pragma unroll
    for (int i = 0; i < 4; i++) {
        int idx = tid + i * 256;
        int r = idx >> 3, c2 = idx & 7;
        cp16(s + r * SAS + c2 * 4, g + (size_t)r * 1024 + c2 * 4);
    }
}

__global__ void __launch_bounds__(256, 1) precompute_kernel() {
    extern __shared__ float sm[];
    float* sAh = sm;
    float* sAl = sm + 2 * PC_TILE_F;
    float* sB  = sm + 4 * PC_TILE_F;

    int tid = threadIdx.x;
    int bx  = blockIdx.x;
    int mt = bx >> 5, nt = bx & 31;        // nt fastest: 32 CTAs share the A tile in L2
    size_t m0 = (size_t)mt * 128;
    int n0 = nt * 128;

    const int lane = tid & 31, gid = lane >> 2, tig = lane & 3;
    const int wid = tid >> 5, wm = wid >> 2, wn = wid & 3;

    const float* Ahg = g_Xhi + m0 * 1024;
    const float* Alg = g_Xlo + m0 * 1024;
    const float* Bg  = g_Wx + (size_t)n0 * 1024;

    float acc[4][4][4] = {};

    pc_load(sAh, Ahg, tid);
    pc_load(sAl, Alg, tid);
    pc_load(sB,  Bg,  tid);
    asm volatile("cp.async.commit_group;\n");

    #pragma unroll 1
    for (int c = 0; c < 32; c++) {
        asm volatile("cp.async.wait_group 0;\n");
        __syncthreads();
        if (c + 1 < 32) {
            int nb = (c + 1) & 1;
            pc_load(sAh + nb * PC_TILE_F, Ahg + (c + 1) * 32, tid);
            pc_load(sAl + nb * PC_TILE_F, Alg + (c + 1) * 32, tid);
            pc_load(sB  + nb * PC_TILE_F, Bg  + (c + 1) * 32, tid);
            asm volatile("cp.async.commit_group;\n");
        }
        const float* ah = sAh + (c & 1) * PC_TILE_F;
        const float* al = sAl + (c & 1) * PC_TILE_F;
        const float* b  = sB  + (c & 1) * PC_TILE_F;
        #pragma unroll
        for (int k8 = 0; k8 < 4; k8++) {
            int k = k8 * 8;
            unsigned bf[4][2];
            #pragma unroll
            for (int ni = 0; ni < 4; ni++) {
                int nr = wn * 32 + ni * 8 + gid;
                bf[ni][0] = __float_as_uint(b[nr * SAS + k + tig]);
                bf[ni][1] = __float_as_uint(b[nr * SAS + k + tig + 4]);
            }
            unsigned af[4][4];
            #pragma unroll
            for (int mi = 0; mi < 4; mi++) {
                int r0 = wm * 64 + mi * 16 + gid;
                af[mi][0] = __float_as_uint(ah[r0 * SAS + k + tig]);
                af[mi][1] = __float_as_uint(ah[(r0 + 8) * SAS + k + tig]);
                af[mi][2] = __float_as_uint(ah[r0 * SAS + k + tig + 4]);
                af[mi][3] = __float_as_uint(ah[(r0 + 8) * SAS + k + tig + 4]);
            }
            #pragma unroll
            for (int mi = 0; mi < 4; mi++)
                #pragma unroll
                for (int ni = 0; ni < 4; ni++)
                    mma8(acc[mi][ni], af[mi], bf[ni]);
            #pragma unroll
            for (int mi = 0; mi < 4; mi++) {
                int r0 = wm * 64 + mi * 16 + gid;
                af[mi][0] = __float_as_uint(al[r0 * SAS + k + tig]);
                af[mi][1] = __float_as_uint(al[(r0 + 8) * SAS + k + tig]);
                af[mi][2] = __float_as_uint(al[r0 * SAS + k + tig + 4]);
                af[mi][3] = __float_as_uint(al[(r0 + 8) * SAS + k + tig + 4]);
            }
            #pragma unroll
            for (int mi = 0; mi < 4; mi++)
                #pragma unroll
                for (int ni = 0; ni < 4; ni++)
                    mma8(acc[mi][ni], af[mi], bf[ni]);
        }
    }

    // epilogue: add bias, write Z
    #pragma unroll
    for (int mi = 0; mi < 4; mi++)
        #pragma unroll
        for (int ni = 0; ni < 4; ni++) {
            size_t row = m0 + wm * 64 + mi * 16 + gid;
            int col = n0 + wn * 32 + ni * 8 + 2 * tig;
            float b0 = g_bias[col], b1 = g_bias[col + 1];
            float2 v0 = make_float2(acc[mi][ni][0] + b0, acc[mi][ni][1] + b1);
            float2 v1 = make_float2(acc[mi][ni][2] + b0, acc[mi][ni][3] + b1);
            *reinterpret_cast<float2*>(&g_Z[row * N4 + col])       = v0;
            *reinterpret_cast<float2*>(&g_Z[(row + 8) * N4 + col]) = v1;
        }
}

// ---------------- kernel 3: persistent recurrent LSTM ----------------
// 128 CTAs, 64x64 tile, 8 warps = 4 K-quarters x 2 N-halves, warp tile 64x32.
// Chunk = 32 smem cols = 4 quarters x 8-wide K slices.
#define LS_TILE_F (64 * SAS)
#define LS_RED_S  68
#define LS_SMEM   ((4 * LS_TILE_F + 64 * LS_RED_S) * 4)

__device__ __forceinline__ void ls_load(float* s, const float* g, int c, int tid) {
    // 64 rows x 32 floats = 512 cp16 / 256 threads; col c8 -> k = (c8>>1)*256 + c*8 + (c8&1)*4
    #pragma unroll
    for (int i = 0; i < 2; i++) {
        int idx = tid + i * 256;
        int r = idx >> 3, c8 = idx & 7;
        int k = (c8 >> 1) * 256 + c * 8 + (c8 & 1) * 4;
        cp16(s + r * SAS + c8 * 4, g + (size_t)r * 1024 + k);
    }
}

__global__ void __launch_bounds__(256, 1) lstm_kernel(float* __restrict__ out) {
    extern __shared__ float sm[];
    float* sA = sm;
    float* sB = sm + 2 * LS_TILE_F;
    float* sR = sm + 4 * LS_TILE_F;

    int tid = threadIdx.x;
    int bx = blockIdx.x;
    int mt = bx >> 6, nt = bx & 63;
    int m0 = mt * 64, n0 = nt * 64;
    const int lane = tid & 31, gid = lane >> 2, tig = lane & 3;
    const int wid = tid >> 5;
    const int ws = wid >> 1, wn = wid & 1;          // K-quarter, N-half
    const int kbase = ws * 8;                        // smem col base for this quarter

    const float* Wb = g_Wh + (size_t)n0 * 1024;

    // elementwise ownership: row r, 4 units starting at jj*4 (local), 16 preact cols
    const int er = tid >> 2, ej = tid & 3;
    const size_t row_g = (size_t)(m0 + er);
    float cst[4] = {0.f, 0.f, 0.f, 0.f};

    for (int t = 0; t < T_SEQ; t++) {
        const float* hin  = g_h[t & 1];
        float*       hout = g_h[(t + 1) & 1];
        const float* Zt   = g_Z + (size_t)t * BATCH * N4;

        // prefetch this thread's Z quadruples (latency hides under the GEMM)
        float4 zf[4];
        {
            const float4* zp = reinterpret_cast<const float4*>(&Zt[row_g * N4 + n0 + ej * 16]);
            #pragma unroll
            for (int i = 0; i < 4; i++) zf[i] = zp[i];
        }

        float acc[4][4][4] = {};

        ls_load(sA, hin + (size_t)m0 * 1024, 0, tid);
        ls_load(sB, Wb, 0, tid);
        asm volatile("cp.async.commit_group;\n");

        #pragma unroll 1
        for (int c = 0; c < 32; c++) {
            asm volatile("cp.async.wait_group 0;\n");
            __syncthreads();
            if (c + 1 < 32) {
                int nb = (c + 1) & 1;
                ls_load(sA + nb * LS_TILE_F, hin + (size_t)m0 * 1024, c + 1, tid);
                ls_load(sB + nb * LS_TILE_F, Wb, c + 1, tid);
                asm volatile("cp.async.commit_group;\n");
            }
            const float* a = sA + (c & 1) * LS_TILE_F;
            const float* b = sB + (c & 1) * LS_TILE_F;
            unsigned bf[4][2];
            #pragma unroll
            for (int ni = 0; ni < 4; ni++) {
                int nr = wn * 32 + ni * 8 + gid;
                bf[ni][0] = __float_as_uint(b[nr * SAS + kbase + tig]);
                bf[ni][1] = __float_as_uint(b[nr * SAS + kbase + tig + 4]);
            }
            unsigned af[4][4];
            #pragma unroll
            for (int mi = 0; mi < 4; mi++) {
                int r0 = mi * 16 + gid;
                af[mi][0] = __float_as_uint(a[r0 * SAS + kbase + tig]);
                af[mi][1] = __float_as_uint(a[(r0 + 8) * SAS + kbase + tig]);
                af[mi][2] = __float_as_uint(a[r0 * SAS + kbase + tig + 4]);
                af[mi][3] = __float_as_uint(a[(r0 + 8) * SAS + kbase + tig + 4]);
            }
            #pragma unroll
            for (int mi = 0; mi < 4; mi++)
                #pragma unroll
                for (int ni = 0; ni < 4; ni++)
                    mma8(acc[mi][ni], af[mi], bf[ni]);
        }

        // staged K-partial reduction into sR (quarters 3 -> 0)
        __syncthreads();
        #pragma unroll
        for (int q = 3; q >= 0; q--) {
            if (ws == q) {
                #pragma unroll
                for (int mi = 0; mi < 4; mi++)
                    #pragma unroll
                    for (int ni = 0; ni < 4; ni++) {
                        int r = mi * 16 + gid;
                        int cc = wn * 32 + ni * 8 + 2 * tig;
                        float* p0 = &sR[r * LS_RED_S + cc];
                        float* p1 = &sR[(r + 8) * LS_RED_S + cc];
                        if (q == 3) {
                            p0[0] = acc[mi][ni][0]; p0[1] = acc[mi][ni][1];
                            p1[0] = acc[mi][ni][2]; p1[1] = acc[mi][ni][3];
                        } else {
                            p0[0] += acc[mi][ni][0]; p0[1] += acc[mi][ni][1];
                            p1[0] += acc[mi][ni][2]; p1[1] += acc[mi][ni][3];
                        }
                    }
            }
            __syncthreads();
        }

        // elementwise: each thread owns 4 complete (f,i,g,o) quadruples + c-state
        {
            float p[16];
            const float* sr = &sR[er * LS_RED_S + ej * 16];
            const float* zz = reinterpret_cast<const float*>(zf);
            #pragma unroll
            for (int i = 0; i < 16; i++) p[i] = sr[i] + zz[i];

            float4 hv, hq;
            float* hvp = reinterpret_cast<float*>(&hv);
            float* hqp = reinterpret_cast<float*>(&hq);
            #pragma unroll
            for (int i = 0; i < 4; i++) {
                float f = sigm(p[4 * i + 0]);
                float ii = sigm(p[4 * i + 1]);
                float gg = tanhf(p[4 * i + 2]);
                float oo = sigm(p[4 * i + 3]);
                float cn = cst[i] * f + ii * gg;
                cst[i] = cn;
                float h = oo * tanhf(cn);
                hvp[i] = h;
                hqp[i] = tf32r(h);
            }
            int u0 = nt * 16 + ej * 4;
            *reinterpret_cast<float4*>(&out[(size_t)t * (BATCH * DOUT) + row_g * DOUT + u0]) = hv;
            *reinterpret_cast<float4*>(&hout[row_g * DOUT + u0]) = hq;
        }

        // grid-wide barrier: all h writes of step t visible before step t+1 reads
        __syncthreads();
        if (tid == 0) {
            __threadfence();
            atomicAdd(&g_bar, 1u);
            unsigned tgt = (unsigned)(t + 1) * GRID_LSTM;
            while (*((volatile unsigned*)&g_bar) < tgt) { }
            __threadfence();
        }
        __syncthreads();
    }
}

// ---------------- launch ----------------
extern "C" void kernel_launch(void* const* d_in, const int* in_sizes, int n_in,
                              void* d_out, int out_size) {
    const float* tokens = (const float*)d_in[0];
    const float* Wf = (const float*)d_in[1]; const float* bf = (const float*)d_in[2];
    const float* Wi = (const float*)d_in[3]; const float* bi = (const float*)d_in[4];
    const float* Wc = (const float*)d_in[5]; const float* bc = (const float*)d_in[6];
    const float* Wo = (const float*)d_in[7]; const float* bo = (const float*)d_in[8];

    cudaFuncSetAttribute(precompute_kernel, cudaFuncAttributeMaxDynamicSharedMemorySize, PC_SMEM);
    cudaFuncSetAttribute(lstm_kernel,       cudaFuncAttributeMaxDynamicSharedMemorySize, LS_SMEM);

    pack_kernel<<<2048, 256>>>(tokens, Wf, bf, Wi, bi, Wc, bc, Wo, bo);
    precompute_kernel<<<512 * 32, 256, PC_SMEM>>>();
    lstm_kernel<<<GRID_LSTM, 256, LS_SMEM>>>((float*)d_out);
}

// round 4
// speedup vs baseline: 1.7451x; 1.7451x over previous
#include <cuda_runtime.h>
#include <cstdint>
#include <cstddef>

#define T_SEQ 512
#define BATCH 128
#define DIN   1024
#define DOUT  1024
#define N4    4096          // 4 gates * DOUT, gate-interleaved: n = unit*4 + gate
#define GRID_LSTM 128

// ---------------- static device scratch (no allocations allowed) ----------------
__device__ __align__(256) float g_Z  [(size_t)T_SEQ * BATCH * N4];   // 1 GiB: x-part preactivations (+bias)
__device__ __align__(256) float g_Wx [(size_t)N4 * DIN];             // packed tf32-rounded x-weights
__device__ __align__(256) float g_Wh [(size_t)N4 * DOUT];            // packed tf32-rounded h-weights
__device__ __align__(256) float g_bias[N4];
__device__ __align__(256) float g_Xhi[(size_t)T_SEQ * BATCH * DIN];  // tf32 hi split of tokens
__device__ __align__(256) float g_Xlo[(size_t)T_SEQ * BATCH * DIN];  // tf32 lo split of tokens
__device__ __align__(256) float g_h  [2][BATCH * DOUT];              // ping-pong hidden state (tf32-rounded)
__device__ unsigned g_bar;                                           // grid barrier counter

// ---------------- helpers ----------------
__device__ __forceinline__ float tf32r(float x) {
    uint32_t u;
    asm("cvt.rna.tf32.f32 %0, %1;" : "=r"(u) : "f"(x));
    return __uint_as_float(u);
}

__device__ __forceinline__ void cp16(float* smem_dst, const float* gsrc) {
    unsigned s = (unsigned)__cvta_generic_to_shared(smem_dst);
    asm volatile("cp.async.cg.shared.global [%0], [%1], 16;\n" :: "r"(s), "l"(gsrc));
}

__device__ __forceinline__ void mma8(float* d, const unsigned* a, const unsigned* b) {
    asm volatile(
        "mma.sync.aligned.m16n8k8.row.col.f32.tf32.tf32.f32 "
        "{%0,%1,%2,%3}, {%4,%5,%6,%7}, {%8,%9}, {%0,%1,%2,%3};\n"
        : "+f"(d[0]), "+f"(d[1]), "+f"(d[2]), "+f"(d[3])
        : "r"(a[0]), "r"(a[1]), "r"(a[2]), "r"(a[3]), "r"(b[0]), "r"(b[1]));
}

__device__ __forceinline__ float sigm(float x) { return 1.f / (1.f + __expf(-x)); }

// ---------------- kernel 1: pack weights / split tokens / reset state ----------------
__global__ void __launch_bounds__(256) pack_kernel(
    const float* __restrict__ tokens,
    const float* __restrict__ Wf, const float* __restrict__ bf,
    const float* __restrict__ Wi, const float* __restrict__ bi,
    const float* __restrict__ Wc, const float* __restrict__ bc,
    const float* __restrict__ Wo, const float* __restrict__ bo)
{
    size_t tid = (size_t)blockIdx.x * blockDim.x + threadIdx.x;
    size_t nth = (size_t)gridDim.x * blockDim.x;
    if (tid == 0) g_bar = 0;   // reset grid barrier every launch (graph replays)

    for (size_t i = tid; i < (size_t)N4 * 1024; i += nth) {
        int n = (int)(i >> 10), k = (int)(i & 1023);
        int u = n >> 2, g = n & 3;
        const float* W = (g == 0) ? Wf : (g == 1) ? Wi : (g == 2) ? Wc : Wo;
        g_Wx[i] = tf32r(W[(size_t)u * 2048 + k]);
        g_Wh[i] = tf32r(W[(size_t)u * 2048 + 1024 + k]);
    }
    for (size_t i = tid; i < (size_t)N4; i += nth) {
        int u = (int)(i >> 2), g = (int)(i & 3);
        const float* bb = (g == 0) ? bf : (g == 1) ? bi : (g == 2) ? bc : bo;
        g_bias[i] = bb[u];
    }
    for (size_t i = tid; i < (size_t)T_SEQ * BATCH * DIN; i += nth) {
        float x  = tokens[i];
        float hi = tf32r(x);
        g_Xhi[i] = hi;
        g_Xlo[i] = tf32r(x - hi);
    }
    for (size_t i = tid; i < (size_t)BATCH * DOUT; i += nth)
        g_h[0][i] = 0.f;   // h0 = 0
}

// ---------------- kernel 2 (v4): Z = (Xhi+Xlo) @ Wx^T + b ----------------
// CTA tile 128x128, 128 threads = 4 warps as 2(M) x 2(N); warp tile 64x64.
// K chunks of 16; Ahi/Alo/B triple, double-buffered; B frags reused for hi+lo.
#define PSAS  20                         // smem row stride (floats), conflict-free
#define PTILE (128 * PSAS)               // floats per 128x16 tile
#define PSMEM (6 * PTILE * 4)            // bytes: 3 tiles x 2 buffers = 61440

__device__ __forceinline__ void pc3_load(float* sb,
                                         const float* __restrict__ Ah,
                                         const float* __restrict__ Al,
                                         const float* __restrict__ B,
                                         int k0, int tid) {
    #pragma unroll
    for (int i = 0; i < 4; i++) {
        int idx = tid + i * 128;
        int r = idx >> 2, c4 = idx & 3;
        cp16(sb + r * PSAS + c4 * 4, Ah + (size_t)r * 1024 + k0 + c4 * 4);
    }
    #pragma unroll
    for (int i = 0; i < 4; i++) {
        int idx = tid + i * 128;
        int r = idx >> 2, c4 = idx & 3;
        cp16(sb + PTILE + r * PSAS + c4 * 4, Al + (size_t)r * 1024 + k0 + c4 * 4);
    }
    #pragma unroll
    for (int i = 0; i < 4; i++) {
        int idx = tid + i * 128;
        int r = idx >> 2, c4 = idx & 3;
        cp16(sb + 2 * PTILE + r * PSAS + c4 * 4, B + (size_t)r * 1024 + k0 + c4 * 4);
    }
}

__global__ void __launch_bounds__(128, 2) precompute_v4() {
    extern __shared__ float sm3[];
    const int tid = threadIdx.x;
    const int bx = blockIdx.x;
    const int mt = bx >> 5, nt = bx & 31;     // nt fastest: 32 CTAs share the A tile in L2
    const size_t m0 = (size_t)mt * 128;
    const int n0 = nt * 128;

    const int lane = tid & 31, gid = lane >> 2, tig = lane & 3;
    const int wid = tid >> 5, wm = wid >> 1, wn = wid & 1;

    const float* Ahg = g_Xhi + m0 * 1024;
    const float* Alg = g_Xlo + m0 * 1024;
    const float* Bg  = g_Wx + (size_t)n0 * 1024;

    float acc[4][8][4] = {};

    pc3_load(sm3, Ahg, Alg, Bg, 0, tid);
    asm volatile("cp.async.commit_group;\n");

    #pragma unroll 1
    for (int c = 0; c < 64; c++) {
        if (c + 1 < 64) {
            pc3_load(sm3 + ((c + 1) & 1) * 3 * PTILE, Ahg, Alg, Bg, (c + 1) * 16, tid);
            asm volatile("cp.async.commit_group;\n");
            asm volatile("cp.async.wait_group 1;\n");
        } else {
            asm volatile("cp.async.wait_group 0;\n");
        }
        __syncthreads();
        const float* base = sm3 + (c & 1) * 3 * PTILE;
        const float* ah = base;
        const float* al = base + PTILE;
        const float* b  = base + 2 * PTILE;

        #pragma unroll
        for (int k8 = 0; k8 < 2; k8++) {
            int k = k8 * 8;
            unsigned bf[8][2];
            #pragma unroll
            for (int ni = 0; ni < 8; ni++) {
                int nr = wn * 64 + ni * 8 + gid;
                bf[ni][0] = __float_as_uint(b[nr * PSAS + k + tig]);
                bf[ni][1] = __float_as_uint(b[nr * PSAS + k + tig + 4]);
            }
            unsigned af[4][4];
            #pragma unroll
            for (int mi = 0; mi < 4; mi++) {
                int r0 = wm * 64 + mi * 16 + gid;
                af[mi][0] = __float_as_uint(ah[r0 * PSAS + k + tig]);
                af[mi][1] = __float_as_uint(ah[(r0 + 8) * PSAS + k + tig]);
                af[mi][2] = __float_as_uint(ah[r0 * PSAS + k + tig + 4]);
                af[mi][3] = __float_as_uint(ah[(r0 + 8) * PSAS + k + tig + 4]);
            }
            #pragma unroll
            for (int mi = 0; mi < 4; mi++)
                #pragma unroll
                for (int ni = 0; ni < 8; ni++)
                    mma8(acc[mi][ni], af[mi], bf[ni]);
            // lo pass reuses the B fragments
            #pragma unroll
            for (int mi = 0; mi < 4; mi++) {
                int r0 = wm * 64 + mi * 16 + gid;
                af[mi][0] = __float_as_uint(al[r0 * PSAS + k + tig]);
                af[mi][1] = __float_as_uint(al[(r0 + 8) * PSAS + k + tig]);
                af[mi][2] = __float_as_uint(al[r0 * PSAS + k + tig + 4]);
                af[mi][3] = __float_as_uint(al[(r0 + 8) * PSAS + k + tig + 4]);
            }
            #pragma unroll
            for (int mi = 0; mi < 4; mi++)
                #pragma unroll
                for (int ni = 0; ni < 8; ni++)
                    mma8(acc[mi][ni], af[mi], bf[ni]);
        }
        __syncthreads();
    }

    // epilogue: add bias, write Z
    #pragma unroll
    for (int mi = 0; mi < 4; mi++)
        #pragma unroll
        for (int ni = 0; ni < 8; ni++) {
            size_t row = m0 + wm * 64 + mi * 16 + gid;
            int col = n0 + wn * 64 + ni * 8 + 2 * tig;
            float b0 = g_bias[col], b1 = g_bias[col + 1];
            float2 v0 = make_float2(acc[mi][ni][0] + b0, acc[mi][ni][1] + b1);
            float2 v1 = make_float2(acc[mi][ni][2] + b0, acc[mi][ni][3] + b1);
            *reinterpret_cast<float2*>(&g_Z[row * N4 + col])       = v0;
            *reinterpret_cast<float2*>(&g_Z[(row + 8) * N4 + col]) = v1;
        }
}

// ---------------- lstm GEMM core (round-1, known-good) ----------------
#define SAS  36               // smem row stride (floats)
#define SBUF (64 * SAS)

__device__ __forceinline__ void load_chunk(float* s, const float* g, int tid) {
    #pragma unroll
    for (int i = 0; i < 2; i++) {
        int idx = tid + i * 256;
        int r = idx >> 3, c = idx & 7;
        cp16(s + r * SAS + c * 4, g + (size_t)r * 1024 + c * 4);
    }
}

__device__ __forceinline__ void gemm64(const float* __restrict__ Ag,
                                       const float* __restrict__ Bg,
                                       float* sA, float* sB,
                                       float acc[2][2][4], int tid) {
    const int lane = tid & 31, gid = lane >> 2, tig = lane & 3;
    const int wid = tid >> 5, wm = wid >> 2, wn = wid & 3;

    load_chunk(sA, Ag, tid);
    load_chunk(sB, Bg, tid);
    asm volatile("cp.async.commit_group;\n");

    #pragma unroll 1
    for (int c = 0; c < 32; c++) {
        if (c + 1 < 32) {
            load_chunk(sA + ((c + 1) & 1) * SBUF, Ag + (c + 1) * 32, tid);
            load_chunk(sB + ((c + 1) & 1) * SBUF, Bg + (c + 1) * 32, tid);
            asm volatile("cp.async.commit_group;\n");
            asm volatile("cp.async.wait_group 1;\n");
        } else {
            asm volatile("cp.async.wait_group 0;\n");
        }
        __syncthreads();
        const float* a = sA + (c & 1) * SBUF;
        const float* b = sB + (c & 1) * SBUF;
        #pragma unroll
        for (int k8 = 0; k8 < 4; k8++) {
            int k = k8 * 8;
            unsigned af[2][4], bb[2][2];
            #pragma unroll
            for (int mi = 0; mi < 2; mi++) {
                int r0 = wm * 32 + mi * 16 + gid;
                af[mi][0] = __float_as_uint(a[r0 * SAS + k + tig]);
                af[mi][1] = __float_as_uint(a[(r0 + 8) * SAS + k + tig]);
                af[mi][2] = __float_as_uint(a[r0 * SAS + k + tig + 4]);
                af[mi][3] = __float_as_uint(a[(r0 + 8) * SAS + k + tig + 4]);
            }
            #pragma unroll
            for (int ni = 0; ni < 2; ni++) {
                int n0_ = wn * 16 + ni * 8 + gid;
                bb[ni][0] = __float_as_uint(b[n0_ * SAS + k + tig]);
                bb[ni][1] = __float_as_uint(b[n0_ * SAS + k + tig + 4]);
            }
            #pragma unroll
            for (int mi = 0; mi < 2; mi++)
                #pragma unroll
                for (int ni = 0; ni < 2; ni++)
                    mma8(acc[mi][ni], af[mi], bb[ni]);
        }
        __syncthreads();
    }
}

// ---------------- kernel 3: persistent recurrent LSTM (round-1, known-good) ----------------
__global__ void __launch_bounds__(256) lstm_kernel(float* __restrict__ out) {
    __shared__ float sA[2 * SBUF], sB[2 * SBUF];
    int tid = threadIdx.x;
    int bx = blockIdx.x;
    int mt = bx >> 6, nt = bx & 63;
    int m0 = mt * 64, n0 = nt * 64;
    const int lane = tid & 31, gid = lane >> 2, tig = lane & 3;
    const int wid = tid >> 5, wm = wid >> 2, wn = wid & 3;
    const float* Wb = g_Wh + (size_t)n0 * 1024;

    float cst[2][2][2] = {};   // c-state (even-tig lanes)

    for (int t = 0; t < T_SEQ; t++) {
        const float* hin  = g_h[t & 1];
        float*       hout = g_h[(t + 1) & 1];
        const float* Zt   = g_Z + (size_t)t * BATCH * N4;

        float acc[2][2][4] = {};
        gemm64(hin + (size_t)m0 * 1024, Wb, sA, sB, acc, tid);

        #pragma unroll
        for (int mi = 0; mi < 2; mi++)
            #pragma unroll
            for (int ni = 0; ni < 2; ni++) {
                int row = m0 + wm * 32 + mi * 16 + gid;
                int col = n0 + wn * 16 + ni * 8 + 2 * tig;
                float2 z0 = *reinterpret_cast<const float2*>(&Zt[(size_t)row * N4 + col]);
                float2 z1 = *reinterpret_cast<const float2*>(&Zt[(size_t)(row + 8) * N4 + col]);
                float v0 = acc[mi][ni][0] + z0.x;
                float v1 = acc[mi][ni][1] + z0.y;
                float v2 = acc[mi][ni][2] + z1.x;
                float v3 = acc[mi][ni][3] + z1.y;
                float p0 = __shfl_xor_sync(0xffffffffu, v0, 1);
                float p1 = __shfl_xor_sync(0xffffffffu, v1, 1);
                float p2 = __shfl_xor_sync(0xffffffffu, v2, 1);
                float p3 = __shfl_xor_sync(0xffffffffu, v3, 1);
                if (!(tig & 1)) {
                    int u = col >> 2;
                    {
                        float f = sigm(v0), ii = sigm(v1), gg = tanhf(p0), oo = sigm(p1);
                        float cn = cst[mi][ni][0] * f + ii * gg;
                        cst[mi][ni][0] = cn;
                        float h = oo * tanhf(cn);
                        out[(size_t)t * (BATCH * DOUT) + (size_t)row * DOUT + u] = h;
                        hout[row * DOUT + u] = tf32r(h);
                    }
                    {
                        float f = sigm(v2), ii = sigm(v3), gg = tanhf(p2), oo = sigm(p3);
                        float cn = cst[mi][ni][1] * f + ii * gg;
                        cst[mi][ni][1] = cn;
                        float h = oo * tanhf(cn);
                        out[(size_t)t * (BATCH * DOUT) + (size_t)(row + 8) * DOUT + u] = h;
                        hout[(row + 8) * DOUT + u] = tf32r(h);
                    }
                }
            }

        __syncthreads();
        if (tid == 0) {
            __threadfence();
            atomicAdd(&g_bar, 1u);
            unsigned tgt = (unsigned)(t + 1) * GRID_LSTM;
            while (*((volatile unsigned*)&g_bar) < tgt) { }
            __threadfence();
        }
        __syncthreads();
    }
}

// ---------------- launch ----------------
extern "C" void kernel_launch(void* const* d_in, const int* in_sizes, int n_in,
                              void* d_out, int out_size) {
    const float* tokens = (const float*)d_in[0];
    const float* Wf = (const float*)d_in[1]; const float* bf = (const float*)d_in[2];
    const float* Wi = (const float*)d_in[3]; const float* bi = (const float*)d_in[4];
    const float* Wc = (const float*)d_in[5]; const float* bc = (const float*)d_in[6];
    const float* Wo = (const float*)d_in[7]; const float* bo = (const float*)d_in[8];

    cudaFuncSetAttribute(precompute_v4, cudaFuncAttributeMaxDynamicSharedMemorySize, PSMEM);

    pack_kernel<<<2048, 256>>>(tokens, Wf, bf, Wi, bi, Wc, bc, Wo, bo);
    precompute_v4<<<512 * 32, 128, PSMEM>>>();
    lstm_kernel<<<GRID_LSTM, 256>>>((float*)d_out);
}

// round 5
// speedup vs baseline: 3.2293x; 1.8505x over previous
#include <cuda_runtime.h>
#include <cuda_fp16.h>
#include <cstdint>
#include <cstddef>

#define T_SEQ 512
#define BATCH 128
#define DIN   1024
#define DOUT  1024
#define N4    4096          // 4 gates * DOUT, gate-interleaved: n = unit*4 + gate
#define GRID_LSTM 128

// ---------------- static device scratch (no allocations allowed) ----------------
__device__ __align__(256) float  g_Z   [(size_t)T_SEQ * BATCH * N4]; // 1 GiB preactivations (+bias)
__device__ __align__(256) __half g_WxH [(size_t)N4 * DIN];           // packed fp16 x-weights
__device__ __align__(256) __half g_WhH [(size_t)N4 * DOUT];          // packed fp16 h-weights
__device__ __align__(256) float  g_bias[N4];
__device__ __align__(256) __half g_XhiH[(size_t)T_SEQ * BATCH * DIN];// fp16 hi split of tokens
__device__ __align__(256) __half g_XloH[(size_t)T_SEQ * BATCH * DIN];// fp16 lo split
__device__ __align__(256) __half g_hH  [2][BATCH * DOUT];            // ping-pong hidden state fp16
__device__ unsigned g_bar;                                           // grid barrier counter

// ---------------- helpers ----------------
__device__ __forceinline__ void cp16(void* smem_dst, const void* gsrc) {
    unsigned s = (unsigned)__cvta_generic_to_shared(smem_dst);
    asm volatile("cp.async.cg.shared.global [%0], [%1], 16;\n" :: "r"(s), "l"(gsrc));
}

__device__ __forceinline__ void ldsm4(unsigned& r0, unsigned& r1, unsigned& r2, unsigned& r3,
                                      uint32_t addr) {
    asm volatile("ldmatrix.sync.aligned.m8n8.x4.shared.b16 {%0,%1,%2,%3}, [%4];"
                 : "=r"(r0), "=r"(r1), "=r"(r2), "=r"(r3) : "r"(addr));
}

__device__ __forceinline__ void mma16(float* d, const unsigned* a, const unsigned* b) {
    asm volatile(
        "mma.sync.aligned.m16n8k16.row.col.f32.f16.f16.f32 "
        "{%0,%1,%2,%3}, {%4,%5,%6,%7}, {%8,%9}, {%0,%1,%2,%3};\n"
        : "+f"(d[0]), "+f"(d[1]), "+f"(d[2]), "+f"(d[3])
        : "r"(a[0]), "r"(a[1]), "r"(a[2]), "r"(a[3]), "r"(b[0]), "r"(b[1]));
}

__device__ __forceinline__ float sigm(float x) { return 1.f / (1.f + __expf(-x)); }

__device__ __forceinline__ uint32_t smem_u32(const void* p) {
    return (uint32_t)__cvta_generic_to_shared(p);
}

// ---------------- kernel 1: pack weights / split tokens / reset state ----------------
__global__ void __launch_bounds__(256) pack_kernel(
    const float* __restrict__ tokens,
    const float* __restrict__ Wf, const float* __restrict__ bf,
    const float* __restrict__ Wi, const float* __restrict__ bi,
    const float* __restrict__ Wc, const float* __restrict__ bc,
    const float* __restrict__ Wo, const float* __restrict__ bo)
{
    size_t tid = (size_t)blockIdx.x * blockDim.x + threadIdx.x;
    size_t nth = (size_t)gridDim.x * blockDim.x;
    if (tid == 0) g_bar = 0;   // reset grid barrier every launch (graph replays)

    for (size_t i = tid; i < (size_t)N4 * 1024; i += nth) {
        int n = (int)(i >> 10), k = (int)(i & 1023);
        int u = n >> 2, g = n & 3;
        const float* W = (g == 0) ? Wf : (g == 1) ? Wi : (g == 2) ? Wc : Wo;
        g_WxH[i] = __float2half_rn(W[(size_t)u * 2048 + k]);
        g_WhH[i] = __float2half_rn(W[(size_t)u * 2048 + 1024 + k]);
    }
    for (size_t i = tid; i < (size_t)N4; i += nth) {
        int u = (int)(i >> 2), g = (int)(i & 3);
        const float* bb = (g == 0) ? bf : (g == 1) ? bi : (g == 2) ? bc : bo;
        g_bias[i] = bb[u];
    }
    for (size_t i = tid; i < (size_t)T_SEQ * BATCH * DIN; i += nth) {
        float x = tokens[i];
        __half hi = __float2half_rn(x);
        g_XhiH[i] = hi;
        g_XloH[i] = __float2half_rn(x - __half2float(hi));
    }
    for (size_t i = tid; i < (size_t)BATCH * DOUT; i += nth)
        g_hH[0][i] = __float2half_rn(0.f);   // h0 = 0
}

// ---------------- kernel 2: fp16 mma: Z = (Xhi+Xlo) @ Wx^T + b ----------------
// CTA tile 128x128, 128 threads = 4 warps 2(M)x2(N); warp tile 64x64; K-chunk 32.
#define PC_SAS  40                    // halfs per smem row (32 data + 8 pad)
#define PC_PT   (128 * PC_SAS)        // halfs per 128x32 tile (5120)
#define PC_SMEM (2 * 3 * PC_PT * 2)   // bytes = 61440

__global__ void __launch_bounds__(128, 2) precompute_fp16() {
    extern __shared__ __half smH[];
    const int tid = threadIdx.x, lane = tid & 31, wid = tid >> 5;
    const int wm = wid >> 1, wn = wid & 1;
    const int gid = lane >> 2, tig = lane & 3;
    const int bx = blockIdx.x;
    const int mt = bx >> 5, nt = bx & 31;        // nt fastest: A tile shared in L2
    const size_t m0 = (size_t)mt * 128;
    const int n0 = nt * 128;

    const __half* Ah = g_XhiH + m0 * 1024;
    const __half* Al = g_XloH + m0 * 1024;
    const __half* Bw = g_WxH + (size_t)n0 * 1024;
    const uint32_t smb = smem_u32(smH);

    // ldmatrix per-thread address components
    const int aR = (lane & 15), aK = ((lane >> 4) << 3);
    const int bR = (lane & 7) + ((lane >> 4) << 3), bK = ((lane >> 3) & 1) << 3;

    float acc[4][8][4] = {};

    // chunk loader (Ahi, Alo, B -> buffer)
    #define PC_LOAD(buf, c) do {                                                   \
        __half* d_ = smH + (buf) * 3 * PC_PT;                                      \
        int k0_ = (c) * 32;                                                        \
        _Pragma("unroll")                                                          \
        for (int i_ = 0; i_ < 4; i_++) { int ix_ = tid + i_ * 128;                 \
            int r_ = ix_ >> 2, s_ = ix_ & 3;                                       \
            cp16(d_ + r_ * PC_SAS + s_ * 8, Ah + (size_t)r_ * 1024 + k0_ + s_ * 8);} \
        _Pragma("unroll")                                                          \
        for (int i_ = 0; i_ < 4; i_++) { int ix_ = tid + i_ * 128;                 \
            int r_ = ix_ >> 2, s_ = ix_ & 3;                                       \
            cp16(d_ + PC_PT + r_ * PC_SAS + s_ * 8, Al + (size_t)r_ * 1024 + k0_ + s_ * 8);} \
        _Pragma("unroll")                                                          \
        for (int i_ = 0; i_ < 4; i_++) { int ix_ = tid + i_ * 128;                 \
            int r_ = ix_ >> 2, s_ = ix_ & 3;                                       \
            cp16(d_ + 2 * PC_PT + r_ * PC_SAS + s_ * 8, Bw + (size_t)r_ * 1024 + k0_ + s_ * 8);} \
        asm volatile("cp.async.commit_group;\n");                                  \
    } while (0)

    PC_LOAD(0, 0);

    #pragma unroll 1
    for (int c = 0; c < 32; c++) {
        asm volatile("cp.async.wait_group 0;\n");
        __syncthreads();                          // chunk c resident; buf (c+1)&1 free
        if (c + 1 < 32) PC_LOAD((c + 1) & 1, c + 1);

        const uint32_t base = smb + (uint32_t)((c & 1) * 3 * PC_PT) * 2;
        #pragma unroll
        for (int kk = 0; kk < 2; kk++) {
            const int ko = kk * 16;
            unsigned bfr[8][2];
            #pragma unroll
            for (int nb = 0; nb < 4; nb++) {
                uint32_t ad = base + 2u * PC_PT * 2 +
                              (uint32_t)((wn * 64 + nb * 16 + bR) * PC_SAS + ko + bK) * 2;
                ldsm4(bfr[2 * nb][0], bfr[2 * nb][1], bfr[2 * nb + 1][0], bfr[2 * nb + 1][1], ad);
            }
            unsigned af[4][4];
            #pragma unroll
            for (int mi = 0; mi < 4; mi++) {
                uint32_t ad = base + (uint32_t)((wm * 64 + mi * 16 + aR) * PC_SAS + ko + aK) * 2;
                ldsm4(af[mi][0], af[mi][1], af[mi][2], af[mi][3], ad);
            }
            #pragma unroll
            for (int mi = 0; mi < 4; mi++)
                #pragma unroll
                for (int ni = 0; ni < 8; ni++)
                    mma16(acc[mi][ni], af[mi], bfr[ni]);
            // lo pass reuses B fragments
            #pragma unroll
            for (int mi = 0; mi < 4; mi++) {
                uint32_t ad = base + (uint32_t)PC_PT * 2 +
                              (uint32_t)((wm * 64 + mi * 16 + aR) * PC_SAS + ko + aK) * 2;
                ldsm4(af[mi][0], af[mi][1], af[mi][2], af[mi][3], ad);
            }
            #pragma unroll
            for (int mi = 0; mi < 4; mi++)
                #pragma unroll
                for (int ni = 0; ni < 8; ni++)
                    mma16(acc[mi][ni], af[mi], bfr[ni]);
        }
    }

    // epilogue: add bias, write Z
    #pragma unroll
    for (int mi = 0; mi < 4; mi++)
        #pragma unroll
        for (int ni = 0; ni < 8; ni++) {
            size_t row = m0 + wm * 64 + mi * 16 + gid;
            int col = n0 + wn * 64 + ni * 8 + 2 * tig;
            float b0 = g_bias[col], b1 = g_bias[col + 1];
            float2 v0 = make_float2(acc[mi][ni][0] + b0, acc[mi][ni][1] + b1);
            float2 v1 = make_float2(acc[mi][ni][2] + b0, acc[mi][ni][3] + b1);
            *reinterpret_cast<float2*>(&g_Z[row * N4 + col])       = v0;
            *reinterpret_cast<float2*>(&g_Z[(row + 8) * N4 + col]) = v1;
        }
}

// ---------------- kernel 3: persistent recurrent LSTM, fp16, smem-resident weights ----
// 128 CTAs (2 mt x 64 nt), 64x64 tile, 8 warps 2(M)x4(N), warp tile 32x16.
// Wh slice (64x1024 fp16 = 128 KB) resident in smem for all 512 steps.
#define LS_BSAS 1032                            // halfs per B row (1024 + 8 pad)
#define LS_ASAS 72                              // halfs per A chunk row (64 + 8 pad)
#define LS_BT   (64 * LS_BSAS)                  // 66048 halfs
#define LS_AT   (64 * LS_ASAS)                  // 4608 halfs
#define LS_SMEM ((LS_BT + 2 * LS_AT) * 2)       // 150528 bytes

__global__ void __launch_bounds__(256) lstm_fp16(float* __restrict__ out) {
    extern __shared__ __half smL[];
    __half* sB = smL;
    __half* sA = smL + LS_BT;

    const int tid = threadIdx.x, lane = tid & 31, wid = tid >> 5;
    const int wm = wid >> 2, wn = wid & 3;
    const int gid = lane >> 2, tig = lane & 3;
    const int bx = blockIdx.x;
    const int mt = bx >> 6, nt = bx & 63;
    const int m0 = mt * 64, n0 = nt * 64;

    const __half* Wb = g_WhH + (size_t)n0 * 1024;
    const uint32_t sBb = smem_u32(sB);
    const uint32_t sAb = smem_u32(sA);

    const int aR = (lane & 15), aK = ((lane >> 4) << 3);
    const int bR = (lane & 7) + ((lane >> 4) << 3), bK = ((lane >> 3) & 1) << 3;

    // preload resident Wh slice: 64 rows x 1024 halfs
    #pragma unroll 4
    for (int i = 0; i < 32; i++) {
        int idx = tid + i * 256;
        int r = idx >> 7, s = idx & 127;
        cp16(sB + r * LS_BSAS + s * 8, Wb + (size_t)r * 1024 + s * 8);
    }
    asm volatile("cp.async.commit_group;\n");
    asm volatile("cp.async.wait_group 0;\n");
    __syncthreads();

    float cst[2][2][2] = {};   // c-state (even-tig lanes)

    for (int t = 0; t < T_SEQ; t++) {
        const __half* hin = g_hH[t & 1];
        __half*      hout = g_hH[(t + 1) & 1];
        const float* Zt   = g_Z + (size_t)t * BATCH * N4;

        // prefetch Z fragments (DRAM latency hides under the GEMM)
        float2 z[2][2][2];
        #pragma unroll
        for (int mi = 0; mi < 2; mi++)
            #pragma unroll
            for (int ni = 0; ni < 2; ni++) {
                int row = m0 + wm * 32 + mi * 16 + gid;
                int col = n0 + wn * 16 + ni * 8 + 2 * tig;
                z[mi][ni][0] = *reinterpret_cast<const float2*>(&Zt[(size_t)row * N4 + col]);
                z[mi][ni][1] = *reinterpret_cast<const float2*>(&Zt[(size_t)(row + 8) * N4 + col]);
            }

        float acc[2][2][4] = {};

        #define LS_LOADA(buf, c) do {                                              \
            __half* d_ = sA + (buf) * LS_AT;                                       \
            _Pragma("unroll")                                                      \
            for (int i_ = 0; i_ < 2; i_++) { int ix_ = tid + i_ * 256;             \
                int r_ = ix_ >> 3, s_ = ix_ & 7;                                   \
                cp16(d_ + r_ * LS_ASAS + s_ * 8,                                   \
                     hin + (size_t)(m0 + r_) * 1024 + (c) * 64 + s_ * 8); }        \
            asm volatile("cp.async.commit_group;\n");                              \
        } while (0)

        LS_LOADA(0, 0);

        #pragma unroll 1
        for (int c = 0; c < 16; c++) {
            asm volatile("cp.async.wait_group 0;\n");
            __syncthreads();
            if (c + 1 < 16) LS_LOADA((c + 1) & 1, c + 1);

            const uint32_t abase = sAb + (uint32_t)((c & 1) * LS_AT) * 2;
            #pragma unroll
            for (int kk = 0; kk < 4; kk++) {
                const int koA = kk * 16;
                const int koB = c * 64 + kk * 16;
                unsigned bfr[2][2];
                {
                    uint32_t ad = sBb + (uint32_t)((wn * 16 + bR) * LS_BSAS + koB + bK) * 2;
                    ldsm4(bfr[0][0], bfr[0][1], bfr[1][0], bfr[1][1], ad);
                }
                unsigned af[2][4];
                #pragma unroll
                for (int mi = 0; mi < 2; mi++) {
                    uint32_t ad = abase + (uint32_t)((wm * 32 + mi * 16 + aR) * LS_ASAS + koA + aK) * 2;
                    ldsm4(af[mi][0], af[mi][1], af[mi][2], af[mi][3], ad);
                }
                #pragma unroll
                for (int mi = 0; mi < 2; mi++)
                    #pragma unroll
                    for (int ni = 0; ni < 2; ni++)
                        mma16(acc[mi][ni], af[mi], bfr[ni]);
            }
        }

        // elementwise LSTM cell (gate pairs in adjacent lanes; shfl_xor(1) completes quads)
        #pragma unroll
        for (int mi = 0; mi < 2; mi++)
            #pragma unroll
            for (int ni = 0; ni < 2; ni++) {
                int row = m0 + wm * 32 + mi * 16 + gid;
                int col = n0 + wn * 16 + ni * 8 + 2 * tig;
                float v0 = acc[mi][ni][0] + z[mi][ni][0].x;
                float v1 = acc[mi][ni][1] + z[mi][ni][0].y;
                float v2 = acc[mi][ni][2] + z[mi][ni][1].x;
                float v3 = acc[mi][ni][3] + z[mi][ni][1].y;
                float p0 = __shfl_xor_sync(0xffffffffu, v0, 1);
                float p1 = __shfl_xor_sync(0xffffffffu, v1, 1);
                float p2 = __shfl_xor_sync(0xffffffffu, v2, 1);
                float p3 = __shfl_xor_sync(0xffffffffu, v3, 1);
                if (!(tig & 1)) {
                    int u = col >> 2;
                    {
                        float f = sigm(v0), ii = sigm(v1), gg = tanhf(p0), oo = sigm(p1);
                        float cn = cst[mi][ni][0] * f + ii * gg;
                        cst[mi][ni][0] = cn;
                        float h = oo * tanhf(cn);
                        out[(size_t)t * (BATCH * DOUT) + (size_t)row * DOUT + u] = h;
                        hout[row * DOUT + u] = __float2half_rn(h);
                    }
                    {
                        float f = sigm(v2), ii = sigm(v3), gg = tanhf(p2), oo = sigm(p3);
                        float cn = cst[mi][ni][1] * f + ii * gg;
                        cst[mi][ni][1] = cn;
                        float h = oo * tanhf(cn);
                        out[(size_t)t * (BATCH * DOUT) + (size_t)(row + 8) * DOUT + u] = h;
                        hout[(row + 8) * DOUT + u] = __float2half_rn(h);
                    }
                }
            }

        // grid-wide barrier: all h writes of step t visible before step t+1 reads
        __syncthreads();
        if (tid == 0) {
            __threadfence();
            atomicAdd(&g_bar, 1u);
            unsigned tgt = (unsigned)(t + 1) * GRID_LSTM;
            while (*((volatile unsigned*)&g_bar) < tgt) { }
            __threadfence();
        }
        __syncthreads();
    }
}

// ---------------- launch ----------------
extern "C" void kernel_launch(void* const* d_in, const int* in_sizes, int n_in,
                              void* d_out, int out_size) {
    const float* tokens = (const float*)d_in[0];
    const float* Wf = (const float*)d_in[1]; const float* bf = (const float*)d_in[2];
    const float* Wi = (const float*)d_in[3]; const float* bi = (const float*)d_in[4];
    const float* Wc = (const float*)d_in[5]; const float* bc = (const float*)d_in[6];
    const float* Wo = (const float*)d_in[7]; const float* bo = (const float*)d_in[8];

    cudaFuncSetAttribute(precompute_fp16, cudaFuncAttributeMaxDynamicSharedMemorySize, PC_SMEM);
    cudaFuncSetAttribute(lstm_fp16,       cudaFuncAttributeMaxDynamicSharedMemorySize, LS_SMEM);

    pack_kernel<<<2048, 256>>>(tokens, Wf, bf, Wi, bi, Wc, bc, Wo, bo);
    precompute_fp16<<<512 * 32, 128, PC_SMEM>>>();
    lstm_fp16<<<GRID_LSTM, 256, LS_SMEM>>>((float*)d_out);
}

// round 6
// speedup vs baseline: 4.2843x; 1.3267x over previous
#include <cuda_runtime.h>
#include <cuda_fp16.h>
#include <cstdint>
#include <cstddef>

#define T_SEQ 512
#define BATCH 128
#define DIN   1024
#define DOUT  1024
#define N4    4096          // 4 gates * DOUT, gate-interleaved: n = unit*4 + gate
#define GRID_LSTM 128

// ---------------- static device scratch (no allocations allowed) ----------------
__device__ __align__(256) float  g_Z   [(size_t)T_SEQ * BATCH * N4]; // 1 GiB preactivations (+bias)
__device__ __align__(256) __half g_WxH [(size_t)N4 * DIN];           // packed fp16 x-weights
__device__ __align__(256) __half g_WhH [(size_t)N4 * DOUT];          // packed fp16 h-weights
__device__ __align__(256) float  g_bias[N4];
__device__ __align__(256) __half g_XhH [(size_t)T_SEQ * BATCH * DIN];// fp16 tokens
__device__ __align__(256) __half g_hH  [2][BATCH * DOUT];            // ping-pong hidden state fp16
__device__ unsigned g_bar2[2][32];                                   // per-mt-group barrier counters (padded)

// ---------------- helpers ----------------
__device__ __forceinline__ void cp16(void* smem_dst, const void* gsrc) {
    unsigned s = (unsigned)__cvta_generic_to_shared(smem_dst);
    asm volatile("cp.async.cg.shared.global [%0], [%1], 16;\n" :: "r"(s), "l"(gsrc));
}

__device__ __forceinline__ void ldsm4(unsigned& r0, unsigned& r1, unsigned& r2, unsigned& r3,
                                      uint32_t addr) {
    asm volatile("ldmatrix.sync.aligned.m8n8.x4.shared.b16 {%0,%1,%2,%3}, [%4];"
                 : "=r"(r0), "=r"(r1), "=r"(r2), "=r"(r3) : "r"(addr));
}

__device__ __forceinline__ void mma16(float* d, const unsigned* a, const unsigned* b) {
    asm volatile(
        "mma.sync.aligned.m16n8k16.row.col.f32.f16.f16.f32 "
        "{%0,%1,%2,%3}, {%4,%5,%6,%7}, {%8,%9}, {%0,%1,%2,%3};\n"
        : "+f"(d[0]), "+f"(d[1]), "+f"(d[2]), "+f"(d[3])
        : "r"(a[0]), "r"(a[1]), "r"(a[2]), "r"(a[3]), "r"(b[0]), "r"(b[1]));
}

__device__ __forceinline__ float sigm(float x) { return 1.f / (1.f + __expf(-x)); }

__device__ __forceinline__ uint32_t smem_u32(const void* p) {
    return (uint32_t)__cvta_generic_to_shared(p);
}

// ---------------- kernel 1: pack weights / convert tokens / reset state ----------------
__global__ void __launch_bounds__(256) pack_kernel(
    const float* __restrict__ tokens,
    const float* __restrict__ Wf, const float* __restrict__ bf,
    const float* __restrict__ Wi, const float* __restrict__ bi,
    const float* __restrict__ Wc, const float* __restrict__ bc,
    const float* __restrict__ Wo, const float* __restrict__ bo)
{
    size_t tid = (size_t)blockIdx.x * blockDim.x + threadIdx.x;
    size_t nth = (size_t)gridDim.x * blockDim.x;
    if (tid < 64) g_bar2[tid >> 5][tid & 31] = 0;   // reset barriers every launch (graph replays)

    for (size_t i = tid; i < (size_t)N4 * 1024; i += nth) {
        int n = (int)(i >> 10), k = (int)(i & 1023);
        int u = n >> 2, g = n & 3;
        const float* W = (g == 0) ? Wf : (g == 1) ? Wi : (g == 2) ? Wc : Wo;
        g_WxH[i] = __float2half_rn(W[(size_t)u * 2048 + k]);
        g_WhH[i] = __float2half_rn(W[(size_t)u * 2048 + 1024 + k]);
    }
    for (size_t i = tid; i < (size_t)N4; i += nth) {
        int u = (int)(i >> 2), g = (int)(i & 3);
        const float* bb = (g == 0) ? bf : (g == 1) ? bi : (g == 2) ? bc : bo;
        g_bias[i] = bb[u];
    }
    for (size_t i = tid; i < (size_t)T_SEQ * BATCH * DIN; i += nth)
        g_XhH[i] = __float2half_rn(tokens[i]);
    for (size_t i = tid; i < (size_t)BATCH * DOUT; i += nth)
        g_hH[0][i] = __float2half_rn(0.f);   // h0 = 0
}

// ---------------- kernel 2: fp16 mma: Z = X @ Wx^T + b ----------------
// CTA tile 128x128, 128 threads = 4 warps 2(M)x2(N); warp tile 64x64; K-chunk 64.
#define PC_SAS  72                    // halfs per smem row (64 data + 8 pad)
#define PC_PT   (128 * PC_SAS)        // halfs per 128x64 tile (9216)
#define PC_SMEM (2 * 2 * PC_PT * 2)   // bytes = 73728 (A,B x double buffer)

__global__ void __launch_bounds__(128, 2) precompute_fp16() {
    extern __shared__ __half smH[];
    const int tid = threadIdx.x, lane = tid & 31, wid = tid >> 5;
    const int wm = wid >> 1, wn = wid & 1;
    const int gid = lane >> 2, tig = lane & 3;
    const int bx = blockIdx.x;
    const int mt = bx >> 5, nt = bx & 31;        // nt fastest: A tile shared in L2
    const size_t m0 = (size_t)mt * 128;
    const int n0 = nt * 128;

    const __half* Ax = g_XhH + m0 * 1024;
    const __half* Bw = g_WxH + (size_t)n0 * 1024;
    const uint32_t smb = smem_u32(smH);

    // ldmatrix per-thread address components
    const int aR = (lane & 15), aK = ((lane >> 4) << 3);
    const int bR = (lane & 7) + ((lane >> 4) << 3), bK = ((lane >> 3) & 1) << 3;

    float acc[4][8][4] = {};

    // chunk loader (A, B -> buffer): 128 rows x 64 halfs each
    #define PC_LOAD(buf, c) do {                                                   \
        __half* d_ = smH + (buf) * 2 * PC_PT;                                      \
        int k0_ = (c) * 64;                                                        \
        _Pragma("unroll")                                                          \
        for (int i_ = 0; i_ < 8; i_++) { int ix_ = tid + i_ * 128;                 \
            int r_ = ix_ >> 3, s_ = ix_ & 7;                                       \
            cp16(d_ + r_ * PC_SAS + s_ * 8, Ax + (size_t)r_ * 1024 + k0_ + s_ * 8);} \
        _Pragma("unroll")                                                          \
        for (int i_ = 0; i_ < 8; i_++) { int ix_ = tid + i_ * 128;                 \
            int r_ = ix_ >> 3, s_ = ix_ & 7;                                       \
            cp16(d_ + PC_PT + r_ * PC_SAS + s_ * 8, Bw + (size_t)r_ * 1024 + k0_ + s_ * 8);} \
        asm volatile("cp.async.commit_group;\n");                                  \
    } while (0)

    PC_LOAD(0, 0);

    #pragma unroll 1
    for (int c = 0; c < 16; c++) {
        asm volatile("cp.async.wait_group 0;\n");
        __syncthreads();                          // chunk c resident; buf (c+1)&1 free
        if (c + 1 < 16) PC_LOAD((c + 1) & 1, c + 1);

        const uint32_t base = smb + (uint32_t)((c & 1) * 2 * PC_PT) * 2;
        #pragma unroll
        for (int kk = 0; kk < 4; kk++) {
            const int ko = kk * 16;
            unsigned bfr[8][2];
            #pragma unroll
            for (int nb = 0; nb < 4; nb++) {
                uint32_t ad = base + (uint32_t)PC_PT * 2 +
                              (uint32_t)((wn * 64 + nb * 16 + bR) * PC_SAS + ko + bK) * 2;
                ldsm4(bfr[2 * nb][0], bfr[2 * nb][1], bfr[2 * nb + 1][0], bfr[2 * nb + 1][1], ad);
            }
            unsigned af[4][4];
            #pragma unroll
            for (int mi = 0; mi < 4; mi++) {
                uint32_t ad = base + (uint32_t)((wm * 64 + mi * 16 + aR) * PC_SAS + ko + aK) * 2;
                ldsm4(af[mi][0], af[mi][1], af[mi][2], af[mi][3], ad);
            }
            #pragma unroll
            for (int mi = 0; mi < 4; mi++)
                #pragma unroll
                for (int ni = 0; ni < 8; ni++)
                    mma16(acc[mi][ni], af[mi], bfr[ni]);
        }
    }

    // epilogue: add bias, write Z
    #pragma unroll
    for (int mi = 0; mi < 4; mi++)
        #pragma unroll
        for (int ni = 0; ni < 8; ni++) {
            size_t row = m0 + wm * 64 + mi * 16 + gid;
            int col = n0 + wn * 64 + ni * 8 + 2 * tig;
            float b0 = g_bias[col], b1 = g_bias[col + 1];
            float2 v0 = make_float2(acc[mi][ni][0] + b0, acc[mi][ni][1] + b1);
            float2 v1 = make_float2(acc[mi][ni][2] + b0, acc[mi][ni][3] + b1);
            *reinterpret_cast<float2*>(&g_Z[row * N4 + col])       = v0;
            *reinterpret_cast<float2*>(&g_Z[(row + 8) * N4 + col]) = v1;
        }
}

// ---------------- kernel 3: persistent recurrent LSTM, fp16, smem-resident weights ----
// 128 CTAs (2 independent mt groups x 64 nt), 64x64 tile, 8 warps 2(M)x4(N), warp 32x16.
// Wh slice (64x1024 fp16) resident in smem; A staged in 4 chunks of 64x256.
#define LS_BSAS 1032                            // halfs per B row (1024 + 8 pad)
#define LS_ASAS 264                             // halfs per A chunk row (256 + 8 pad)
#define LS_BT   (64 * LS_BSAS)                  // 66048 halfs
#define LS_AT   (64 * LS_ASAS)                  // 16896 halfs
#define LS_SMEM ((LS_BT + 2 * LS_AT) * 2)       // 199680 bytes

__global__ void __launch_bounds__(256) lstm_fp16(float* __restrict__ out) {
    extern __shared__ __half smL[];
    __half* sB = smL;
    __half* sA = smL + LS_BT;

    const int tid = threadIdx.x, lane = tid & 31, wid = tid >> 5;
    const int wm = wid >> 2, wn = wid & 3;
    const int gid = lane >> 2, tig = lane & 3;
    const int bx = blockIdx.x;
    const int mt = bx >> 6, nt = bx & 63;
    const int m0 = mt * 64, n0 = nt * 64;

    const __half* Wb = g_WhH + (size_t)n0 * 1024;
    const uint32_t sBb = smem_u32(sB);
    const uint32_t sAb = smem_u32(sA);
    volatile unsigned* barp = (volatile unsigned*)&g_bar2[mt][0];

    const int aR = (lane & 15), aK = ((lane >> 4) << 3);
    const int bR = (lane & 7) + ((lane >> 4) << 3), bK = ((lane >> 3) & 1) << 3;

    // preload resident Wh slice: 64 rows x 1024 halfs
    #pragma unroll 4
    for (int i = 0; i < 32; i++) {
        int idx = tid + i * 256;
        int r = idx >> 7, s = idx & 127;
        cp16(sB + r * LS_BSAS + s * 8, Wb + (size_t)r * 1024 + s * 8);
    }
    asm volatile("cp.async.commit_group;\n");
    asm volatile("cp.async.wait_group 0;\n");
    __syncthreads();

    float cst[2][2][2] = {};   // c-state (even-tig lanes)

    for (int t = 0; t < T_SEQ; t++) {
        const __half* hin = g_hH[t & 1];
        __half*      hout = g_hH[(t + 1) & 1];
        const float* Zt   = g_Z + (size_t)t * BATCH * N4;

        // prefetch Z fragments (DRAM latency hides under the GEMM)
        float2 z[2][2][2];
        #pragma unroll
        for (int mi = 0; mi < 2; mi++)
            #pragma unroll
            for (int ni = 0; ni < 2; ni++) {
                int row = m0 + wm * 32 + mi * 16 + gid;
                int col = n0 + wn * 16 + ni * 8 + 2 * tig;
                z[mi][ni][0] = *reinterpret_cast<const float2*>(&Zt[(size_t)row * N4 + col]);
                z[mi][ni][1] = *reinterpret_cast<const float2*>(&Zt[(size_t)(row + 8) * N4 + col]);
            }

        float acc[2][2][4] = {};

        // A chunk: 64 rows x 256 halfs
        #define LS_LOADA(buf, c) do {                                              \
            __half* d_ = sA + (buf) * LS_AT;                                       \
            _Pragma("unroll")                                                      \
            for (int i_ = 0; i_ < 8; i_++) { int ix_ = tid + i_ * 256;             \
                int r_ = ix_ >> 5, s_ = ix_ & 31;                                  \
                cp16(d_ + r_ * LS_ASAS + s_ * 8,                                   \
                     hin + (size_t)(m0 + r_) * 1024 + (c) * 256 + s_ * 8); }       \
            asm volatile("cp.async.commit_group;\n");                              \
        } while (0)

        LS_LOADA(0, 0);

        #pragma unroll 1
        for (int c = 0; c < 4; c++) {
            asm volatile("cp.async.wait_group 0;\n");
            __syncthreads();
            if (c + 1 < 4) LS_LOADA((c + 1) & 1, c + 1);

            const uint32_t abase = sAb + (uint32_t)((c & 1) * LS_AT) * 2;
            #pragma unroll
            for (int kk = 0; kk < 16; kk++) {
                const int koA = kk * 16;
                const int koB = c * 256 + kk * 16;
                unsigned bfr[2][2];
                {
                    uint32_t ad = sBb + (uint32_t)((wn * 16 + bR) * LS_BSAS + koB + bK) * 2;
                    ldsm4(bfr[0][0], bfr[0][1], bfr[1][0], bfr[1][1], ad);
                }
                unsigned af[2][4];
                #pragma unroll
                for (int mi = 0; mi < 2; mi++) {
                    uint32_t ad = abase + (uint32_t)((wm * 32 + mi * 16 + aR) * LS_ASAS + koA + aK) * 2;
                    ldsm4(af[mi][0], af[mi][1], af[mi][2], af[mi][3], ad);
                }
                #pragma unroll
                for (int mi = 0; mi < 2; mi++)
                    #pragma unroll
                    for (int ni = 0; ni < 2; ni++)
                        mma16(acc[mi][ni], af[mi], bfr[ni]);
            }
        }

        // elementwise LSTM cell (gate pairs in adjacent lanes; shfl_xor(1) completes quads)
        #pragma unroll
        for (int mi = 0; mi < 2; mi++)
            #pragma unroll
            for (int ni = 0; ni < 2; ni++) {
                int row = m0 + wm * 32 + mi * 16 + gid;
                int col = n0 + wn * 16 + ni * 8 + 2 * tig;
                float v0 = acc[mi][ni][0] + z[mi][ni][0].x;
                float v1 = acc[mi][ni][1] + z[mi][ni][0].y;
                float v2 = acc[mi][ni][2] + z[mi][ni][1].x;
                float v3 = acc[mi][ni][3] + z[mi][ni][1].y;
                float p0 = __shfl_xor_sync(0xffffffffu, v0, 1);
                float p1 = __shfl_xor_sync(0xffffffffu, v1, 1);
                float p2 = __shfl_xor_sync(0xffffffffu, v2, 1);
                float p3 = __shfl_xor_sync(0xffffffffu, v3, 1);
                if (!(tig & 1)) {
                    int u = col >> 2;
                    {
                        float f = sigm(v0), ii = sigm(v1), gg = tanhf(p0), oo = sigm(p1);
                        float cn = cst[mi][ni][0] * f + ii * gg;
                        cst[mi][ni][0] = cn;
                        float h = oo * tanhf(cn);
                        out[(size_t)t * (BATCH * DOUT) + (size_t)row * DOUT + u] = h;
                        hout[row * DOUT + u] = __float2half_rn(h);
                    }
                    {
                        float f = sigm(v2), ii = sigm(v3), gg = tanhf(p2), oo = sigm(p3);
                        float cn = cst[mi][ni][1] * f + ii * gg;
                        cst[mi][ni][1] = cn;
                        float h = oo * tanhf(cn);
                        out[(size_t)t * (BATCH * DOUT) + (size_t)(row + 8) * DOUT + u] = h;
                        hout[(row + 8) * DOUT + u] = __float2half_rn(h);
                    }
                }
            }

        // per-group barrier (64 CTAs): h(t) of this mt group visible before step t+1
        __syncthreads();
        if (tid == 0) {
            __threadfence();
            atomicAdd((unsigned*)barp, 1u);
            unsigned tgt = (unsigned)(t + 1) * (GRID_LSTM / 2);
            while (*barp < tgt) { }
            __threadfence();
        }
        __syncthreads();
    }
}

// ---------------- launch ----------------
extern "C" void kernel_launch(void* const* d_in, const int* in_sizes, int n_in,
                              void* d_out, int out_size) {
    const float* tokens = (const float*)d_in[0];
    const float* Wf = (const float*)d_in[1]; const float* bf = (const float*)d_in[2];
    const float* Wi = (const float*)d_in[3]; const float* bi = (const float*)d_in[4];
    const float* Wc = (const float*)d_in[5]; const float* bc = (const float*)d_in[6];
    const float* Wo = (const float*)d_in[7]; const float* bo = (const float*)d_in[8];

    cudaFuncSetAttribute(precompute_fp16, cudaFuncAttributeMaxDynamicSharedMemorySize, PC_SMEM);
    cudaFuncSetAttribute(lstm_fp16,       cudaFuncAttributeMaxDynamicSharedMemorySize, LS_SMEM);

    pack_kernel<<<2048, 256>>>(tokens, Wf, bf, Wi, bi, Wc, bc, Wo, bo);
    precompute_fp16<<<512 * 32, 128, PC_SMEM>>>();
    lstm_fp16<<<GRID_LSTM, 256, LS_SMEM>>>((float*)d_out);
}